// round 1
// baseline (speedup 1.0000x reference)
#include <cuda_runtime.h>
#include <math.h>

// Problem constants
#define T_TOK 1024
#define H_DIM 1024
#define I_DIM 512
#define N_EXP 16
#define TOPK  4
#define NPAIR (T_TOK * TOPK)   // 4096 (token, expert-slot) pairs, always all used

// ----------------------------------------------------------------------------
// Scratch (static __device__ globals; no allocations allowed)
// ----------------------------------------------------------------------------
__device__ int   g_count[N_EXP];
__device__ int   g_cursor[N_EXP];
__device__ int   g_offset[N_EXP + 1];
__device__ int   g_tok[NPAIR];       // pair slot -> token id
__device__ int   g_pos_of[NPAIR];    // (t*K+k) -> pair slot
__device__ float g_h[NPAIR * I_DIM];     // 8 MB: silu(gate)*up per pair
__device__ float g_pout[NPAIR * H_DIM];  // 16 MB: per-pair down-proj output

// ----------------------------------------------------------------------------
// Routing
// ----------------------------------------------------------------------------
__global__ void zero_kernel() {
    int i = threadIdx.x;
    if (i < N_EXP) { g_count[i] = 0; g_cursor[i] = 0; }
}

__global__ void count_kernel(const int* __restrict__ idx) {
    int i = blockIdx.x * blockDim.x + threadIdx.x;
    if (i < NPAIR) atomicAdd(&g_count[idx[i]], 1);
}

__global__ void offset_kernel() {
    if (threadIdx.x == 0 && blockIdx.x == 0) {
        int acc = 0;
        for (int e = 0; e < N_EXP; e++) { g_offset[e] = acc; acc += g_count[e]; }
        g_offset[N_EXP] = acc;  // == NPAIR
    }
}

__global__ void scatter_kernel(const int* __restrict__ idx) {
    int i = blockIdx.x * blockDim.x + threadIdx.x;
    if (i < NPAIR) {
        int e   = idx[i];
        int pos = g_offset[e] + atomicAdd(&g_cursor[e], 1);
        g_tok[pos]  = i >> 2;   // token id (i = t*TOPK + k)
        g_pos_of[i] = pos;
    }
}

// ----------------------------------------------------------------------------
// GEMM1: for each routed pair p (token t, expert e):
//   g_h[p, n] = silu(x_t . Wg[e,n,:]) * (x_t . Wu[e,n,:]),  n in [0, I)
// Wg = gate_up[e, 0:I, :], Wu = gate_up[e, I:2I, :]
// Tile: 64 pairs x 64 cols, BK=16, 256 threads, 4x4 micro-tile (two accumulators)
// ----------------------------------------------------------------------------
__global__ __launch_bounds__(256) void gemm1_kernel(
    const float* __restrict__ hidden, const float* __restrict__ gate_up)
{
    const int e     = blockIdx.z;
    const int start = g_offset[e];
    const int nrows = g_offset[e + 1] - start;
    const int row0  = blockIdx.y * 64;
    if (row0 >= nrows) return;
    const int col0 = blockIdx.x * 64;

    __shared__ float As[16][68];
    __shared__ float Bg[16][68];
    __shared__ float Bu[16][68];

    const int tid = threadIdx.x;
    const int tx  = tid & 15;          // N micro-index (cols)
    const int ty  = tid >> 4;          // M micro-index (rows)

    // loader mapping: each thread loads one float4 per tile per matrix
    const int lr = tid >> 2;           // 0..63 : row within tile
    const int lk = (tid & 3) * 4;      // 0,4,8,12 : k offset

    int tokRow = -1;
    if (row0 + lr < nrows) tokRow = g_tok[start + row0 + lr];
    const float* Aptr  = hidden + (size_t)(tokRow < 0 ? 0 : tokRow) * H_DIM + lk;
    const float* Bgptr = gate_up + ((size_t)e * 2 * I_DIM + (col0 + lr)) * H_DIM + lk;
    const float* Buptr = gate_up + ((size_t)e * 2 * I_DIM + (I_DIM + col0 + lr)) * H_DIM + lk;

    float accg[4][4] = {};
    float accu[4][4] = {};

    for (int kk = 0; kk < H_DIM; kk += 16) {
        float4 a4 = make_float4(0.f, 0.f, 0.f, 0.f);
        if (tokRow >= 0) a4 = *(const float4*)(Aptr + kk);
        const float4 g4 = *(const float4*)(Bgptr + kk);
        const float4 u4 = *(const float4*)(Buptr + kk);
        __syncthreads();
        As[lk + 0][lr] = a4.x; As[lk + 1][lr] = a4.y; As[lk + 2][lr] = a4.z; As[lk + 3][lr] = a4.w;
        Bg[lk + 0][lr] = g4.x; Bg[lk + 1][lr] = g4.y; Bg[lk + 2][lr] = g4.z; Bg[lk + 3][lr] = g4.w;
        Bu[lk + 0][lr] = u4.x; Bu[lk + 1][lr] = u4.y; Bu[lk + 2][lr] = u4.z; Bu[lk + 3][lr] = u4.w;
        __syncthreads();
        #pragma unroll
        for (int k = 0; k < 16; k++) {
            const float4 av = *(const float4*)(&As[k][ty * 4]);
            const float4 gv = *(const float4*)(&Bg[k][tx * 4]);
            const float4 uv = *(const float4*)(&Bu[k][tx * 4]);
            const float a[4] = {av.x, av.y, av.z, av.w};
            const float g[4] = {gv.x, gv.y, gv.z, gv.w};
            const float u[4] = {uv.x, uv.y, uv.z, uv.w};
            #pragma unroll
            for (int i = 0; i < 4; i++)
                #pragma unroll
                for (int j = 0; j < 4; j++) {
                    accg[i][j] = fmaf(a[i], g[j], accg[i][j]);
                    accu[i][j] = fmaf(a[i], u[j], accu[i][j]);
                }
        }
    }

    // epilogue: silu(gate) * up -> g_h
    #pragma unroll
    for (int i = 0; i < 4; i++) {
        const int m = ty * 4 + i;
        if (row0 + m < nrows) {
            const int pos = start + row0 + m;
            float4 r;
            {
                float g = accg[i][0]; r.x = (g / (1.f + __expf(-g))) * accu[i][0];
                g = accg[i][1];       r.y = (g / (1.f + __expf(-g))) * accu[i][1];
                g = accg[i][2];       r.z = (g / (1.f + __expf(-g))) * accu[i][2];
                g = accg[i][3];       r.w = (g / (1.f + __expf(-g))) * accu[i][3];
            }
            *(float4*)(g_h + (size_t)pos * I_DIM + col0 + tx * 4) = r;
        }
    }
}

// ----------------------------------------------------------------------------
// GEMM2: g_pout[p, n] = g_h[p, :] . down[e, n, :],  n in [0, H)
// Rows are contiguous within an expert segment (no gather needed).
// ----------------------------------------------------------------------------
__global__ __launch_bounds__(256) void gemm2_kernel(const float* __restrict__ down)
{
    const int e     = blockIdx.z;
    const int start = g_offset[e];
    const int nrows = g_offset[e + 1] - start;
    const int row0  = blockIdx.y * 64;
    if (row0 >= nrows) return;
    const int col0 = blockIdx.x * 64;   // H-dim tile

    __shared__ float As[16][68];
    __shared__ float Bs[16][68];

    const int tid = threadIdx.x;
    const int tx  = tid & 15;
    const int ty  = tid >> 4;
    const int lr  = tid >> 2;
    const int lk  = (tid & 3) * 4;

    const bool rowValid = (row0 + lr < nrows);
    const float* Aptr = g_h + (size_t)(start + row0 + (rowValid ? lr : 0)) * I_DIM + lk;
    const float* Bptr = down + ((size_t)e * H_DIM + (col0 + lr)) * I_DIM + lk;

    float acc[4][4] = {};

    for (int kk = 0; kk < I_DIM; kk += 16) {
        float4 a4 = make_float4(0.f, 0.f, 0.f, 0.f);
        if (rowValid) a4 = *(const float4*)(Aptr + kk);
        const float4 b4 = *(const float4*)(Bptr + kk);
        __syncthreads();
        As[lk + 0][lr] = a4.x; As[lk + 1][lr] = a4.y; As[lk + 2][lr] = a4.z; As[lk + 3][lr] = a4.w;
        Bs[lk + 0][lr] = b4.x; Bs[lk + 1][lr] = b4.y; Bs[lk + 2][lr] = b4.z; Bs[lk + 3][lr] = b4.w;
        __syncthreads();
        #pragma unroll
        for (int k = 0; k < 16; k++) {
            const float4 av = *(const float4*)(&As[k][ty * 4]);
            const float4 bv = *(const float4*)(&Bs[k][tx * 4]);
            const float a[4] = {av.x, av.y, av.z, av.w};
            const float b[4] = {bv.x, bv.y, bv.z, bv.w};
            #pragma unroll
            for (int i = 0; i < 4; i++)
                #pragma unroll
                for (int j = 0; j < 4; j++)
                    acc[i][j] = fmaf(a[i], b[j], acc[i][j]);
        }
    }

    #pragma unroll
    for (int i = 0; i < 4; i++) {
        const int m = ty * 4 + i;
        if (row0 + m < nrows) {
            const int pos = start + row0 + m;
            float4 r = make_float4(acc[i][0], acc[i][1], acc[i][2], acc[i][3]);
            *(float4*)(g_pout + (size_t)pos * H_DIM + col0 + tx * 4) = r;
        }
    }
}

// ----------------------------------------------------------------------------
// Reduce: out[t, h] = sum_k w[t,k] * g_pout[pos_of[t,k], h]
// Fixed k-order -> fully deterministic (no float atomics anywhere).
// ----------------------------------------------------------------------------
__global__ void reduce_kernel(const float* __restrict__ wts, float* __restrict__ out)
{
    const int i = blockIdx.x * blockDim.x + threadIdx.x;   // over T*H/4
    if (i >= T_TOK * H_DIM / 4) return;
    const int t  = i / (H_DIM / 4);
    const int h4 = (i % (H_DIM / 4)) * 4;

    float4 acc = make_float4(0.f, 0.f, 0.f, 0.f);
    #pragma unroll
    for (int k = 0; k < TOPK; k++) {
        const int   pos = g_pos_of[t * TOPK + k];
        const float w   = wts[t * TOPK + k];
        const float4 v  = *(const float4*)(g_pout + (size_t)pos * H_DIM + h4);
        acc.x = fmaf(w, v.x, acc.x);
        acc.y = fmaf(w, v.y, acc.y);
        acc.z = fmaf(w, v.z, acc.z);
        acc.w = fmaf(w, v.w, acc.w);
    }
    *(float4*)(out + (size_t)t * H_DIM + h4) = acc;
}

// ----------------------------------------------------------------------------
// Launch (graph-capturable: kernel launches only, default stream)
// ----------------------------------------------------------------------------
extern "C" void kernel_launch(void* const* d_in, const int* in_sizes, int n_in,
                              void* d_out, int out_size)
{
    const float* hidden  = (const float*)d_in[0];
    const int*   idx     = (const int*)  d_in[1];
    const float* wts     = (const float*)d_in[2];
    const float* gate_up = (const float*)d_in[3];
    const float* down    = (const float*)d_in[4];
    float*       out     = (float*)d_out;

    zero_kernel<<<1, 32>>>();
    count_kernel<<<(NPAIR + 255) / 256, 256>>>(idx);
    offset_kernel<<<1, 1>>>();
    scatter_kernel<<<(NPAIR + 255) / 256, 256>>>(idx);

    dim3 g1(I_DIM / 64, NPAIR / 64, N_EXP);   // (8, 64, 16); extra tiles early-exit
    gemm1_kernel<<<g1, 256>>>(hidden, gate_up);

    dim3 g2(H_DIM / 64, NPAIR / 64, N_EXP);   // (16, 64, 16)
    gemm2_kernel<<<g2, 256>>>(down);

    reduce_kernel<<<(T_TOK * H_DIM / 4 + 255) / 256, 256>>>(wts, out);
}

// round 4
// speedup vs baseline: 1.5877x; 1.5877x over previous
#include <cuda_runtime.h>
#include <cuda_bf16.h>
#include <cstdint>
#include <math.h>

// Problem constants
#define T_TOK 1024
#define H_DIM 1024
#define I_DIM 512
#define N_EXP 16
#define TOPK  4
#define NPAIR (T_TOK * TOPK)   // 4096

// ============================================================================
// Scratch (__device__ globals; allocations are forbidden)
// ============================================================================
__device__ int   g_count[N_EXP];
__device__ int   g_cursor[N_EXP];
__device__ int   g_offset[N_EXP + 1];
__device__ int   g_tok[NPAIR];
__device__ int   g_pos_of[NPAIR];

__device__ __nv_bfloat16 g_Xhi[T_TOK * H_DIM];
__device__ __nv_bfloat16 g_Xlo[T_TOK * H_DIM];
__device__ __nv_bfloat16 g_GUhi[N_EXP * 2 * I_DIM * H_DIM];
__device__ __nv_bfloat16 g_GUlo[N_EXP * 2 * I_DIM * H_DIM];
__device__ __nv_bfloat16 g_Dhi[N_EXP * H_DIM * I_DIM];
__device__ __nv_bfloat16 g_Dlo[N_EXP * H_DIM * I_DIM];
__device__ __nv_bfloat16 g_Hhi[NPAIR * I_DIM];
__device__ __nv_bfloat16 g_Hlo[NPAIR * I_DIM];
__device__ float         g_pout[NPAIR * H_DIM];

// ============================================================================
// Small PTX helpers (all legal on plain compute_103: sm_80-era features)
// ============================================================================
__device__ __forceinline__ uint32_t smem_to_u32(const void* p) {
    uint32_t a;
    asm("{ .reg .u64 t; cvta.to.shared.u64 t, %1; cvt.u32.u64 %0, t; }" : "=r"(a) : "l"(p));
    return a;
}
__device__ __forceinline__ void cp16(uint32_t saddr, const void* g, int szbytes) {
    asm volatile("cp.async.cg.shared.global [%0], [%1], 16, %2;"
                 :: "r"(saddr), "l"(g), "r"(szbytes) : "memory");
}
#define CP_COMMIT() asm volatile("cp.async.commit_group;" ::: "memory")
#define CP_WAIT1()  asm volatile("cp.async.wait_group 1;" ::: "memory")
#define CP_WAIT0()  asm volatile("cp.async.wait_group 0;" ::: "memory")

// mma.sync m16n8k16 bf16 -> fp32  (A row-major frag, B col-major frag)
__device__ __forceinline__ void mma16816(float* c, const uint32_t* a, uint32_t b0, uint32_t b1) {
    asm volatile(
        "mma.sync.aligned.m16n8k16.row.col.f32.bf16.bf16.f32 "
        "{%0,%1,%2,%3}, {%4,%5,%6,%7}, {%8,%9}, {%0,%1,%2,%3};"
        : "+f"(c[0]), "+f"(c[1]), "+f"(c[2]), "+f"(c[3])
        : "r"(a[0]), "r"(a[1]), "r"(a[2]), "r"(a[3]), "r"(b0), "r"(b1));
}

// Tile smem layout: [128 rows][32 bf16] = 64B/row, 4x 16B chunks per row,
// chunk swizzle: chunk' = chunk ^ (row & 3)
__device__ __forceinline__ uint32_t chunk_off(int r, int c4) {
    return (uint32_t)(r * 64 + ((c4 ^ (r & 3)) << 4));
}
__device__ __forceinline__ uint32_t elem_off(int r, int c) {   // c: bf16 col 0..31, even
    return (uint32_t)(r * 64 + (((c >> 3) ^ (r & 3)) << 4) + (c & 7) * 2);
}
__device__ __forceinline__ uint32_t lds_u32(const char* base, uint32_t off) {
    return *reinterpret_cast<const uint32_t*>(base + off);
}

// Stage layout: A_hi | A_lo | B_hi | B_lo, each 128x32 bf16 = 8KB
#define SA_HI 0
#define SA_LO 8192
#define SB_HI 16384
#define SB_LO 24576
#define ST_SZ 32768
#define SM_TOTAL (2 * ST_SZ)

// ============================================================================
// Routing
// ============================================================================
__global__ void zero_kernel() {
    int i = threadIdx.x;
    if (i < N_EXP) { g_count[i] = 0; g_cursor[i] = 0; }
}
__global__ void count_kernel(const int* __restrict__ idx) {
    int i = blockIdx.x * blockDim.x + threadIdx.x;
    if (i < NPAIR) atomicAdd(&g_count[idx[i]], 1);
}
__global__ void offset_kernel() {
    if (threadIdx.x == 0 && blockIdx.x == 0) {
        int acc = 0;
        for (int e = 0; e < N_EXP; e++) { g_offset[e] = acc; acc += g_count[e]; }
        g_offset[N_EXP] = acc;
    }
}
__global__ void scatter_kernel(const int* __restrict__ idx) {
    int i = blockIdx.x * blockDim.x + threadIdx.x;
    if (i < NPAIR) {
        int e   = idx[i];
        int pos = g_offset[e] + atomicAdd(&g_cursor[e], 1);
        g_tok[pos]  = i >> 2;
        g_pos_of[i] = pos;
    }
}

// ============================================================================
// fp32 -> (bf16 hi, bf16 lo) split, vectorized
// ============================================================================
__global__ void split_kernel(const float* __restrict__ src,
                             __nv_bfloat16* __restrict__ hi,
                             __nv_bfloat16* __restrict__ lo, int n4) {
    int i = blockIdx.x * blockDim.x + threadIdx.x;
    if (i >= n4) return;
    float4 v = ((const float4*)src)[i];
    float f[4] = {v.x, v.y, v.z, v.w};
    uint32_t hp[2], lp[2];
    #pragma unroll
    for (int q = 0; q < 2; q++) {
        __nv_bfloat16 h0 = __float2bfloat16(f[2 * q]);
        __nv_bfloat16 h1 = __float2bfloat16(f[2 * q + 1]);
        __nv_bfloat16 l0 = __float2bfloat16(f[2 * q] - __bfloat162float(h0));
        __nv_bfloat16 l1 = __float2bfloat16(f[2 * q + 1] - __bfloat162float(h1));
        hp[q] = (uint32_t)__bfloat16_as_ushort(h0) | ((uint32_t)__bfloat16_as_ushort(h1) << 16);
        lp[q] = (uint32_t)__bfloat16_as_ushort(l0) | ((uint32_t)__bfloat16_as_ushort(l1) << 16);
    }
    ((uint2*)hi)[i] = make_uint2(hp[0], hp[1]);
    ((uint2*)lo)[i] = make_uint2(lp[0], lp[1]);
}

// ============================================================================
// GEMM1: 128 pairs x 64 I-cols (gate/up interleaved as 128 B-rows), K = 1024.
// bf16x3 via mma.sync; fused silu(gate)*up epilogue -> g_Hhi/g_Hlo.
// ============================================================================
__global__ __launch_bounds__(256) void gemm1_mma() {
    const int e     = blockIdx.z;
    const int start = g_offset[e];
    const int nrows = g_offset[e + 1] - start;
    const int row0  = blockIdx.y * 128;
    if (row0 >= nrows) return;
    const int col0 = blockIdx.x * 64;          // logical I columns

    extern __shared__ char smem[];
    const uint32_t sbu = smem_to_u32(smem);
    const int tid  = threadIdx.x;
    const int wid  = tid >> 5, lane = tid & 31;
    const int g    = lane >> 2, tg = lane & 3;
    const int wm   = wid & 3;                  // 4 warps over M (32 rows each)
    const int wn   = wid >> 2;                 // 2 warps over N (64 smem-cols each)

    // loader mapping: thread t owns chunks (r, c4) = (t>>2, t&3) and (t>>2 + 64, t&3)
    const int lr = tid >> 2, c4 = tid & 3;
    const bool v0 = (row0 + lr) < nrows;
    const bool v1 = (row0 + lr + 64) < nrows;
    const int tok0 = v0 ? g_tok[start + row0 + lr] : 0;
    const int tok1 = v1 ? g_tok[start + row0 + lr + 64] : 0;
    const __nv_bfloat16* a0h = g_Xhi + (size_t)tok0 * H_DIM;
    const __nv_bfloat16* a0l = g_Xlo + (size_t)tok0 * H_DIM;
    const __nv_bfloat16* a1h = g_Xhi + (size_t)tok1 * H_DIM;
    const __nv_bfloat16* a1l = g_Xlo + (size_t)tok1 * H_DIM;
    // B: smem row n -> gate_up row e*1024 + col0 + (n>>1) + (n&1)*512
    const int bn0 = lr, bn1 = lr + 64;
    const size_t br0 = ((size_t)e * 1024 + col0 + (bn0 >> 1) + (bn0 & 1) * 512) * H_DIM;
    const size_t br1 = ((size_t)e * 1024 + col0 + (bn1 >> 1) + (bn1 & 1) * 512) * H_DIM;

    const uint32_t oA0 = chunk_off(lr, c4),      oA1 = chunk_off(lr + 64, c4);

    float acc[2][8][4];
    #pragma unroll
    for (int a = 0; a < 2; a++)
        #pragma unroll
        for (int b = 0; b < 8; b++)
            #pragma unroll
            for (int c = 0; c < 4; c++) acc[a][b][c] = 0.f;

    const int NCH = H_DIM / 32;   // 32 chunks
    // preload stage 0
    {
        const int gc = 0 + c4 * 8;
        uint32_t s = sbu;
        cp16(s + SA_HI + oA0, a0h + gc, v0 ? 16 : 0);
        cp16(s + SA_HI + oA1, a1h + gc, v1 ? 16 : 0);
        cp16(s + SA_LO + oA0, a0l + gc, v0 ? 16 : 0);
        cp16(s + SA_LO + oA1, a1l + gc, v1 ? 16 : 0);
        cp16(s + SB_HI + oA0, g_GUhi + br0 + gc, 16);
        cp16(s + SB_HI + oA1, g_GUhi + br1 + gc, 16);
        cp16(s + SB_LO + oA0, g_GUlo + br0 + gc, 16);
        cp16(s + SB_LO + oA1, g_GUlo + br1 + gc, 16);
        CP_COMMIT();
    }

    #pragma unroll 1
    for (int ch = 0; ch < NCH; ch++) {
        if (ch + 1 < NCH) {
            const int gc = (ch + 1) * 32 + c4 * 8;
            uint32_t s = sbu + ((ch + 1) & 1) * ST_SZ;
            cp16(s + SA_HI + oA0, a0h + gc, v0 ? 16 : 0);
            cp16(s + SA_HI + oA1, a1h + gc, v1 ? 16 : 0);
            cp16(s + SA_LO + oA0, a0l + gc, v0 ? 16 : 0);
            cp16(s + SA_LO + oA1, a1l + gc, v1 ? 16 : 0);
            cp16(s + SB_HI + oA0, g_GUhi + br0 + gc, 16);
            cp16(s + SB_HI + oA1, g_GUhi + br1 + gc, 16);
            cp16(s + SB_LO + oA0, g_GUlo + br0 + gc, 16);
            cp16(s + SB_LO + oA1, g_GUlo + br1 + gc, 16);
            CP_COMMIT();
            CP_WAIT1();
        } else {
            CP_WAIT0();
        }
        __syncthreads();
        const char* s = smem + (ch & 1) * ST_SZ;
        #pragma unroll
        for (int kh = 0; kh < 32; kh += 16) {
            uint32_t Ah[2][4], Al[2][4];
            #pragma unroll
            for (int mt = 0; mt < 2; mt++) {
                const int r0 = wm * 32 + mt * 16 + g;
                const int kl = kh + tg * 2, kk = kh + tg * 2 + 8;
                Ah[mt][0] = lds_u32(s, SA_HI + elem_off(r0,     kl));
                Ah[mt][1] = lds_u32(s, SA_HI + elem_off(r0 + 8, kl));
                Ah[mt][2] = lds_u32(s, SA_HI + elem_off(r0,     kk));
                Ah[mt][3] = lds_u32(s, SA_HI + elem_off(r0 + 8, kk));
                Al[mt][0] = lds_u32(s, SA_LO + elem_off(r0,     kl));
                Al[mt][1] = lds_u32(s, SA_LO + elem_off(r0 + 8, kl));
                Al[mt][2] = lds_u32(s, SA_LO + elem_off(r0,     kk));
                Al[mt][3] = lds_u32(s, SA_LO + elem_off(r0 + 8, kk));
            }
            #pragma unroll
            for (int nt = 0; nt < 8; nt++) {
                const int n = wn * 64 + nt * 8 + g;
                const int kl = kh + tg * 2, kk = kh + tg * 2 + 8;
                const uint32_t Bh0 = lds_u32(s, SB_HI + elem_off(n, kl));
                const uint32_t Bh1 = lds_u32(s, SB_HI + elem_off(n, kk));
                const uint32_t Bl0 = lds_u32(s, SB_LO + elem_off(n, kl));
                const uint32_t Bl1 = lds_u32(s, SB_LO + elem_off(n, kk));
                #pragma unroll
                for (int mt = 0; mt < 2; mt++) {
                    mma16816(acc[mt][nt], Ah[mt], Bh0, Bh1);
                    mma16816(acc[mt][nt], Al[mt], Bh0, Bh1);
                    mma16816(acc[mt][nt], Ah[mt], Bl0, Bl1);
                }
            }
        }
        __syncthreads();
    }

    // Epilogue: (c0,c1)=(gate,up) of one logical col; silu fuse; split store.
    #pragma unroll
    for (int mt = 0; mt < 2; mt++) {
        #pragma unroll
        for (int nt = 0; nt < 8; nt++) {
            const int r  = wm * 32 + mt * 16 + g;
            const int jj = col0 + ((wn * 64 + nt * 8 + tg * 2) >> 1);
            const float* c = acc[mt][nt];
            #pragma unroll
            for (int hrow = 0; hrow < 2; hrow++) {
                const int rr = r + hrow * 8;
                if (row0 + rr < nrows) {
                    const float gate = c[hrow * 2], up = c[hrow * 2 + 1];
                    const float h = gate / (1.f + __expf(-gate)) * up;
                    const __nv_bfloat16 hh = __float2bfloat16(h);
                    const __nv_bfloat16 hl = __float2bfloat16(h - __bfloat162float(hh));
                    const size_t o = (size_t)(start + row0 + rr) * I_DIM + jj;
                    g_Hhi[o] = hh;
                    g_Hlo[o] = hl;
                }
            }
        }
    }
}

// ============================================================================
// GEMM2: 128 pairs x 128 H-cols, K = 512, bf16x3; fp32 out -> g_pout.
// ============================================================================
__global__ __launch_bounds__(256) void gemm2_mma() {
    const int e     = blockIdx.z;
    const int start = g_offset[e];
    const int nrows = g_offset[e + 1] - start;
    const int row0  = blockIdx.y * 128;
    if (row0 >= nrows) return;
    const int col0 = blockIdx.x * 128;

    extern __shared__ char smem[];
    const uint32_t sbu = smem_to_u32(smem);
    const int tid  = threadIdx.x;
    const int wid  = tid >> 5, lane = tid & 31;
    const int g    = lane >> 2, tg = lane & 3;
    const int wm   = wid & 3, wn = wid >> 2;

    const int lr = tid >> 2, c4 = tid & 3;
    const bool v0 = (row0 + lr) < nrows;
    const bool v1 = (row0 + lr + 64) < nrows;
    const size_t ar0 = (size_t)(start + row0 + (v0 ? lr : 0)) * I_DIM;
    const size_t ar1 = (size_t)(start + row0 + (v1 ? lr + 64 : 0)) * I_DIM;
    const size_t br0 = ((size_t)e * H_DIM + col0 + lr) * I_DIM;
    const size_t br1 = ((size_t)e * H_DIM + col0 + lr + 64) * I_DIM;

    const uint32_t oA0 = chunk_off(lr, c4), oA1 = chunk_off(lr + 64, c4);

    float acc[2][8][4];
    #pragma unroll
    for (int a = 0; a < 2; a++)
        #pragma unroll
        for (int b = 0; b < 8; b++)
            #pragma unroll
            for (int c = 0; c < 4; c++) acc[a][b][c] = 0.f;

    const int NCH = I_DIM / 32;   // 16
    {
        const int gc = c4 * 8;
        uint32_t s = sbu;
        cp16(s + SA_HI + oA0, g_Hhi + ar0 + gc, v0 ? 16 : 0);
        cp16(s + SA_HI + oA1, g_Hhi + ar1 + gc, v1 ? 16 : 0);
        cp16(s + SA_LO + oA0, g_Hlo + ar0 + gc, v0 ? 16 : 0);
        cp16(s + SA_LO + oA1, g_Hlo + ar1 + gc, v1 ? 16 : 0);
        cp16(s + SB_HI + oA0, g_Dhi + br0 + gc, 16);
        cp16(s + SB_HI + oA1, g_Dhi + br1 + gc, 16);
        cp16(s + SB_LO + oA0, g_Dlo + br0 + gc, 16);
        cp16(s + SB_LO + oA1, g_Dlo + br1 + gc, 16);
        CP_COMMIT();
    }

    #pragma unroll 1
    for (int ch = 0; ch < NCH; ch++) {
        if (ch + 1 < NCH) {
            const int gc = (ch + 1) * 32 + c4 * 8;
            uint32_t s = sbu + ((ch + 1) & 1) * ST_SZ;
            cp16(s + SA_HI + oA0, g_Hhi + ar0 + gc, v0 ? 16 : 0);
            cp16(s + SA_HI + oA1, g_Hhi + ar1 + gc, v1 ? 16 : 0);
            cp16(s + SA_LO + oA0, g_Hlo + ar0 + gc, v0 ? 16 : 0);
            cp16(s + SA_LO + oA1, g_Hlo + ar1 + gc, v1 ? 16 : 0);
            cp16(s + SB_HI + oA0, g_Dhi + br0 + gc, 16);
            cp16(s + SB_HI + oA1, g_Dhi + br1 + gc, 16);
            cp16(s + SB_LO + oA0, g_Dlo + br0 + gc, 16);
            cp16(s + SB_LO + oA1, g_Dlo + br1 + gc, 16);
            CP_COMMIT();
            CP_WAIT1();
        } else {
            CP_WAIT0();
        }
        __syncthreads();
        const char* s = smem + (ch & 1) * ST_SZ;
        #pragma unroll
        for (int kh = 0; kh < 32; kh += 16) {
            uint32_t Ah[2][4], Al[2][4];
            #pragma unroll
            for (int mt = 0; mt < 2; mt++) {
                const int r0 = wm * 32 + mt * 16 + g;
                const int kl = kh + tg * 2, kk = kh + tg * 2 + 8;
                Ah[mt][0] = lds_u32(s, SA_HI + elem_off(r0,     kl));
                Ah[mt][1] = lds_u32(s, SA_HI + elem_off(r0 + 8, kl));
                Ah[mt][2] = lds_u32(s, SA_HI + elem_off(r0,     kk));
                Ah[mt][3] = lds_u32(s, SA_HI + elem_off(r0 + 8, kk));
                Al[mt][0] = lds_u32(s, SA_LO + elem_off(r0,     kl));
                Al[mt][1] = lds_u32(s, SA_LO + elem_off(r0 + 8, kl));
                Al[mt][2] = lds_u32(s, SA_LO + elem_off(r0,     kk));
                Al[mt][3] = lds_u32(s, SA_LO + elem_off(r0 + 8, kk));
            }
            #pragma unroll
            for (int nt = 0; nt < 8; nt++) {
                const int n = wn * 64 + nt * 8 + g;
                const int kl = kh + tg * 2, kk = kh + tg * 2 + 8;
                const uint32_t Bh0 = lds_u32(s, SB_HI + elem_off(n, kl));
                const uint32_t Bh1 = lds_u32(s, SB_HI + elem_off(n, kk));
                const uint32_t Bl0 = lds_u32(s, SB_LO + elem_off(n, kl));
                const uint32_t Bl1 = lds_u32(s, SB_LO + elem_off(n, kk));
                #pragma unroll
                for (int mt = 0; mt < 2; mt++) {
                    mma16816(acc[mt][nt], Ah[mt], Bh0, Bh1);
                    mma16816(acc[mt][nt], Al[mt], Bh0, Bh1);
                    mma16816(acc[mt][nt], Ah[mt], Bl0, Bl1);
                }
            }
        }
        __syncthreads();
    }

    #pragma unroll
    for (int mt = 0; mt < 2; mt++) {
        #pragma unroll
        for (int nt = 0; nt < 8; nt++) {
            const int r   = wm * 32 + mt * 16 + g;
            const int col = col0 + wn * 64 + nt * 8 + tg * 2;
            const float* c = acc[mt][nt];
            #pragma unroll
            for (int hrow = 0; hrow < 2; hrow++) {
                const int rr = r + hrow * 8;
                if (row0 + rr < nrows) {
                    float2 v = make_float2(c[hrow * 2], c[hrow * 2 + 1]);
                    *(float2*)(g_pout + (size_t)(start + row0 + rr) * H_DIM + col) = v;
                }
            }
        }
    }
}

// ============================================================================
// Reduce: out[t,h] = sum_k w[t,k] * g_pout[pos_of[t,k], h]  (deterministic)
// ============================================================================
__global__ void reduce_kernel(const float* __restrict__ wts, float* __restrict__ out) {
    const int i = blockIdx.x * blockDim.x + threadIdx.x;
    if (i >= T_TOK * H_DIM / 4) return;
    const int t  = i / (H_DIM / 4);
    const int h4 = (i % (H_DIM / 4)) * 4;
    float4 acc = make_float4(0.f, 0.f, 0.f, 0.f);
    #pragma unroll
    for (int k = 0; k < TOPK; k++) {
        const int   pos = g_pos_of[t * TOPK + k];
        const float w   = wts[t * TOPK + k];
        const float4 v  = *(const float4*)(g_pout + (size_t)pos * H_DIM + h4);
        acc.x = fmaf(w, v.x, acc.x);
        acc.y = fmaf(w, v.y, acc.y);
        acc.z = fmaf(w, v.z, acc.z);
        acc.w = fmaf(w, v.w, acc.w);
    }
    *(float4*)(out + (size_t)t * H_DIM + h4) = acc;
}

// ============================================================================
// Launch (graph-capturable: kernel launches only)
// ============================================================================
extern "C" void kernel_launch(void* const* d_in, const int* in_sizes, int n_in,
                              void* d_out, int out_size)
{
    const float* hidden  = (const float*)d_in[0];
    const int*   idx     = (const int*)  d_in[1];
    const float* wts     = (const float*)d_in[2];
    const float* gate_up = (const float*)d_in[3];
    const float* down    = (const float*)d_in[4];
    float*       out     = (float*)d_out;

    static bool attr_done = false;
    if (!attr_done) {
        cudaFuncSetAttribute(gemm1_mma, cudaFuncAttributeMaxDynamicSharedMemorySize, SM_TOTAL);
        cudaFuncSetAttribute(gemm2_mma, cudaFuncAttributeMaxDynamicSharedMemorySize, SM_TOTAL);
        attr_done = true;
    }

    // routing
    zero_kernel<<<1, 32>>>();
    count_kernel<<<(NPAIR + 255) / 256, 256>>>(idx);
    offset_kernel<<<1, 1>>>();
    scatter_kernel<<<(NPAIR + 255) / 256, 256>>>(idx);

    // fp32 -> bf16 hi/lo splits
    {
        __nv_bfloat16 *xh, *xl, *gh, *gl, *dh, *dl;
        cudaGetSymbolAddress((void**)&xh, g_Xhi);  cudaGetSymbolAddress((void**)&xl, g_Xlo);
        cudaGetSymbolAddress((void**)&gh, g_GUhi); cudaGetSymbolAddress((void**)&gl, g_GUlo);
        cudaGetSymbolAddress((void**)&dh, g_Dhi);  cudaGetSymbolAddress((void**)&dl, g_Dlo);
        const int n4x = T_TOK * H_DIM / 4;
        const int n4g = N_EXP * 2 * I_DIM * H_DIM / 4;
        const int n4d = N_EXP * H_DIM * I_DIM / 4;
        split_kernel<<<(n4x + 255) / 256, 256>>>(hidden,  xh, xl, n4x);
        split_kernel<<<(n4g + 255) / 256, 256>>>(gate_up, gh, gl, n4g);
        split_kernel<<<(n4d + 255) / 256, 256>>>(down,    dh, dl, n4d);
    }

    // GEMM1: (I/64 col tiles, M tiles, experts)
    dim3 g1(I_DIM / 64, NPAIR / 128, N_EXP);
    gemm1_mma<<<g1, 256, SM_TOTAL>>>();

    // GEMM2: (H/128 col tiles, M tiles, experts)
    dim3 g2(H_DIM / 128, NPAIR / 128, N_EXP);
    gemm2_mma<<<g2, 256, SM_TOTAL>>>();

    reduce_kernel<<<(T_TOK * H_DIM / 4 + 255) / 256, 256>>>(wts, out);
}

// round 5
// speedup vs baseline: 2.0637x; 1.2998x over previous
#include <cuda_runtime.h>
#include <cuda_fp16.h>
#include <cstdint>
#include <math.h>

// Problem constants
#define T_TOK 1024
#define H_DIM 1024
#define I_DIM 512
#define N_EXP 16
#define TOPK  4
#define NPAIR (T_TOK * TOPK)   // 4096

// ============================================================================
// Scratch (__device__ globals; allocations are forbidden)
// ============================================================================
__device__ int g_offset[N_EXP + 1];
__device__ int g_tok[NPAIR];
__device__ int g_pos_of[NPAIR];

__device__ __half g_Xh[T_TOK * H_DIM];                 // hidden, fp16 hi only
__device__ __half g_GUh[N_EXP * 2 * I_DIM * H_DIM];    // gate_up hi
__device__ __half g_GUl[N_EXP * 2 * I_DIM * H_DIM];    // gate_up lo
__device__ __half g_Dh[N_EXP * H_DIM * I_DIM];         // down hi
__device__ __half g_Dl[N_EXP * H_DIM * I_DIM];         // down lo
__device__ __half g_Hh[NPAIR * I_DIM];                 // silu(g)*u, fp16 hi only
__device__ float  g_pout[NPAIR * H_DIM];

// ============================================================================
// PTX helpers (sm_80-era features only — legal on plain compute_103)
// ============================================================================
__device__ __forceinline__ uint32_t smem_to_u32(const void* p) {
    uint32_t a;
    asm("{ .reg .u64 t; cvta.to.shared.u64 t, %1; cvt.u32.u64 %0, t; }" : "=r"(a) : "l"(p));
    return a;
}
__device__ __forceinline__ void cp16(uint32_t saddr, const void* g, int szbytes) {
    asm volatile("cp.async.cg.shared.global [%0], [%1], 16, %2;"
                 :: "r"(saddr), "l"(g), "r"(szbytes) : "memory");
}
#define CP_COMMIT() asm volatile("cp.async.commit_group;" ::: "memory")
#define CP_WAIT1()  asm volatile("cp.async.wait_group 1;" ::: "memory")
#define CP_WAIT0()  asm volatile("cp.async.wait_group 0;" ::: "memory")

// mma.sync m16n8k16 fp16 -> fp32
__device__ __forceinline__ void mma16816(float* c, const uint32_t* a, uint32_t b0, uint32_t b1) {
    asm volatile(
        "mma.sync.aligned.m16n8k16.row.col.f32.f16.f16.f32 "
        "{%0,%1,%2,%3}, {%4,%5,%6,%7}, {%8,%9}, {%0,%1,%2,%3};"
        : "+f"(c[0]), "+f"(c[1]), "+f"(c[2]), "+f"(c[3])
        : "r"(a[0]), "r"(a[1]), "r"(a[2]), "r"(a[3]), "r"(b0), "r"(b1));
}

// Tile smem: [128 rows][32 fp16] = 64B/row, 4x 16B chunks/row, chunk' = chunk ^ (row&3)
__device__ __forceinline__ uint32_t chunk_off(int r, int c4) {
    return (uint32_t)(r * 64 + ((c4 ^ (r & 3)) << 4));
}
__device__ __forceinline__ uint32_t elem_off(int r, int c) {   // c: fp16 col, even
    return (uint32_t)(r * 64 + (((c >> 3) ^ (r & 3)) << 4) + (c & 7) * 2);
}
__device__ __forceinline__ uint32_t lds_u32(const char* base, uint32_t off) {
    return *reinterpret_cast<const uint32_t*>(base + off);
}

// Stage layout: A_hi | B_hi | B_lo, each 128x32 fp16 = 8KB
#define SA_HI 0
#define SB_HI 8192
#define SB_LO 16384
#define ST_SZ 24576
#define SM_TOTAL (2 * ST_SZ)   // 48KB

// ============================================================================
// Routing: single-block count -> prefix -> scatter (1 launch)
// ============================================================================
__global__ void routing_kernel(const int* __restrict__ idx) {
    __shared__ int cnt[N_EXP];
    __shared__ int off[N_EXP];
    const int tid = threadIdx.x;   // 256 threads
    if (tid < N_EXP) cnt[tid] = 0;
    __syncthreads();
    #pragma unroll
    for (int j = 0; j < NPAIR / 256; j++)
        atomicAdd(&cnt[idx[tid + j * 256]], 1);
    __syncthreads();
    if (tid == 0) {
        int acc = 0;
        for (int e = 0; e < N_EXP; e++) { off[e] = acc; g_offset[e] = acc; acc += cnt[e]; }
        g_offset[N_EXP] = acc;
    }
    __syncthreads();
    if (tid < N_EXP) cnt[tid] = 0;   // reuse as cursors
    __syncthreads();
    #pragma unroll
    for (int j = 0; j < NPAIR / 256; j++) {
        const int i = tid + j * 256;
        const int e = idx[i];
        const int pos = off[e] + atomicAdd(&cnt[e], 1);
        g_tok[pos]  = i >> 2;
        g_pos_of[i] = pos;
    }
}

// ============================================================================
// fp32 -> fp16 splits
// ============================================================================
__global__ void split2_kernel(const float* __restrict__ src,
                              __half* __restrict__ hi, __half* __restrict__ lo, int n4) {
    int i = blockIdx.x * blockDim.x + threadIdx.x;
    if (i >= n4) return;
    float4 v = ((const float4*)src)[i];
    float f[4] = {v.x, v.y, v.z, v.w};
    __half h[4], l[4];
    #pragma unroll
    for (int q = 0; q < 4; q++) {
        h[q] = __float2half_rn(f[q]);
        l[q] = __float2half_rn(f[q] - __half2float(h[q]));
    }
    uint32_t hp0 = (uint32_t)__half_as_ushort(h[0]) | ((uint32_t)__half_as_ushort(h[1]) << 16);
    uint32_t hp1 = (uint32_t)__half_as_ushort(h[2]) | ((uint32_t)__half_as_ushort(h[3]) << 16);
    uint32_t lp0 = (uint32_t)__half_as_ushort(l[0]) | ((uint32_t)__half_as_ushort(l[1]) << 16);
    uint32_t lp1 = (uint32_t)__half_as_ushort(l[2]) | ((uint32_t)__half_as_ushort(l[3]) << 16);
    ((uint2*)hi)[i] = make_uint2(hp0, hp1);
    ((uint2*)lo)[i] = make_uint2(lp0, lp1);
}
__global__ void split1_kernel(const float* __restrict__ src, __half* __restrict__ hi, int n4) {
    int i = blockIdx.x * blockDim.x + threadIdx.x;
    if (i >= n4) return;
    float4 v = ((const float4*)src)[i];
    __half h0 = __float2half_rn(v.x), h1 = __float2half_rn(v.y);
    __half h2 = __float2half_rn(v.z), h3 = __float2half_rn(v.w);
    uint32_t p0 = (uint32_t)__half_as_ushort(h0) | ((uint32_t)__half_as_ushort(h1) << 16);
    uint32_t p1 = (uint32_t)__half_as_ushort(h2) | ((uint32_t)__half_as_ushort(h3) << 16);
    ((uint2*)hi)[i] = make_uint2(p0, p1);
}

// ============================================================================
// GEMM1: 128 pairs x 64 I-cols (gate/up interleaved as 128 B-rows), K = 1024
// 2-pass fp16: D = A_hi*(B_hi + B_lo).  Fused silu(gate)*up -> g_Hh (fp16).
// ============================================================================
__global__ __launch_bounds__(256) void gemm1_mma() {
    const int e     = blockIdx.z;
    const int start = g_offset[e];
    const int nrows = g_offset[e + 1] - start;
    const int row0  = blockIdx.y * 128;
    if (row0 >= nrows) return;
    const int col0 = blockIdx.x * 64;

    extern __shared__ char smem[];
    const uint32_t sbu = smem_to_u32(smem);
    const int tid  = threadIdx.x;
    const int wid  = tid >> 5, lane = tid & 31;
    const int g    = lane >> 2, tg = lane & 3;
    const int wm   = wid & 3, wn = wid >> 2;

    const int lr = tid >> 2, c4 = tid & 3;
    const bool v0 = (row0 + lr) < nrows;
    const bool v1 = (row0 + lr + 64) < nrows;
    const int tok0 = v0 ? g_tok[start + row0 + lr] : 0;
    const int tok1 = v1 ? g_tok[start + row0 + lr + 64] : 0;
    const __half* a0 = g_Xh + (size_t)tok0 * H_DIM;
    const __half* a1 = g_Xh + (size_t)tok1 * H_DIM;
    const int bn0 = lr, bn1 = lr + 64;
    const size_t br0 = ((size_t)e * 1024 + col0 + (bn0 >> 1) + (bn0 & 1) * 512) * H_DIM;
    const size_t br1 = ((size_t)e * 1024 + col0 + (bn1 >> 1) + (bn1 & 1) * 512) * H_DIM;

    const uint32_t oA0 = chunk_off(lr, c4), oA1 = chunk_off(lr + 64, c4);

    float acc[2][8][4];
    #pragma unroll
    for (int a = 0; a < 2; a++)
        #pragma unroll
        for (int b = 0; b < 8; b++)
            #pragma unroll
            for (int c = 0; c < 4; c++) acc[a][b][c] = 0.f;

    const int NCH = H_DIM / 32;
    {
        const int gc = c4 * 8;
        uint32_t s = sbu;
        cp16(s + SA_HI + oA0, a0 + gc, v0 ? 16 : 0);
        cp16(s + SA_HI + oA1, a1 + gc, v1 ? 16 : 0);
        cp16(s + SB_HI + oA0, g_GUh + br0 + gc, 16);
        cp16(s + SB_HI + oA1, g_GUh + br1 + gc, 16);
        cp16(s + SB_LO + oA0, g_GUl + br0 + gc, 16);
        cp16(s + SB_LO + oA1, g_GUl + br1 + gc, 16);
        CP_COMMIT();
    }

    #pragma unroll 1
    for (int ch = 0; ch < NCH; ch++) {
        if (ch + 1 < NCH) {
            const int gc = (ch + 1) * 32 + c4 * 8;
            uint32_t s = sbu + ((ch + 1) & 1) * ST_SZ;
            cp16(s + SA_HI + oA0, a0 + gc, v0 ? 16 : 0);
            cp16(s + SA_HI + oA1, a1 + gc, v1 ? 16 : 0);
            cp16(s + SB_HI + oA0, g_GUh + br0 + gc, 16);
            cp16(s + SB_HI + oA1, g_GUh + br1 + gc, 16);
            cp16(s + SB_LO + oA0, g_GUl + br0 + gc, 16);
            cp16(s + SB_LO + oA1, g_GUl + br1 + gc, 16);
            CP_COMMIT();
            CP_WAIT1();
        } else {
            CP_WAIT0();
        }
        __syncthreads();
        const char* s = smem + (ch & 1) * ST_SZ;
        #pragma unroll
        for (int kh = 0; kh < 32; kh += 16) {
            uint32_t Ah[2][4];
            const int kl = kh + tg * 2, kk = kh + tg * 2 + 8;
            #pragma unroll
            for (int mt = 0; mt < 2; mt++) {
                const int r0 = wm * 32 + mt * 16 + g;
                Ah[mt][0] = lds_u32(s, SA_HI + elem_off(r0,     kl));
                Ah[mt][1] = lds_u32(s, SA_HI + elem_off(r0 + 8, kl));
                Ah[mt][2] = lds_u32(s, SA_HI + elem_off(r0,     kk));
                Ah[mt][3] = lds_u32(s, SA_HI + elem_off(r0 + 8, kk));
            }
            #pragma unroll
            for (int nt = 0; nt < 8; nt++) {
                const int n = wn * 64 + nt * 8 + g;
                const uint32_t Bh0 = lds_u32(s, SB_HI + elem_off(n, kl));
                const uint32_t Bh1 = lds_u32(s, SB_HI + elem_off(n, kk));
                const uint32_t Bl0 = lds_u32(s, SB_LO + elem_off(n, kl));
                const uint32_t Bl1 = lds_u32(s, SB_LO + elem_off(n, kk));
                #pragma unroll
                for (int mt = 0; mt < 2; mt++) {
                    mma16816(acc[mt][nt], Ah[mt], Bh0, Bh1);
                    mma16816(acc[mt][nt], Ah[mt], Bl0, Bl1);
                }
            }
        }
        __syncthreads();
    }

    // Epilogue: (c0,c1)=(gate,up); silu fuse; fp16 store.
    #pragma unroll
    for (int mt = 0; mt < 2; mt++) {
        #pragma unroll
        for (int nt = 0; nt < 8; nt++) {
            const int r  = wm * 32 + mt * 16 + g;
            const int jj = col0 + ((wn * 64 + nt * 8 + tg * 2) >> 1);
            const float* c = acc[mt][nt];
            #pragma unroll
            for (int hrow = 0; hrow < 2; hrow++) {
                const int rr = r + hrow * 8;
                if (row0 + rr < nrows) {
                    const float gate = c[hrow * 2], up = c[hrow * 2 + 1];
                    const float h = gate / (1.f + __expf(-gate)) * up;
                    g_Hh[(size_t)(start + row0 + rr) * I_DIM + jj] = __float2half_rn(h);
                }
            }
        }
    }
}

// ============================================================================
// GEMM2: 128 pairs x 128 H-cols, K = 512, 2-pass fp16 -> g_pout (fp32)
// ============================================================================
__global__ __launch_bounds__(256) void gemm2_mma() {
    const int e     = blockIdx.z;
    const int start = g_offset[e];
    const int nrows = g_offset[e + 1] - start;
    const int row0  = blockIdx.y * 128;
    if (row0 >= nrows) return;
    const int col0 = blockIdx.x * 128;

    extern __shared__ char smem[];
    const uint32_t sbu = smem_to_u32(smem);
    const int tid  = threadIdx.x;
    const int wid  = tid >> 5, lane = tid & 31;
    const int g    = lane >> 2, tg = lane & 3;
    const int wm   = wid & 3, wn = wid >> 2;

    const int lr = tid >> 2, c4 = tid & 3;
    const bool v0 = (row0 + lr) < nrows;
    const bool v1 = (row0 + lr + 64) < nrows;
    const size_t ar0 = (size_t)(start + row0 + (v0 ? lr : 0)) * I_DIM;
    const size_t ar1 = (size_t)(start + row0 + (v1 ? lr + 64 : 0)) * I_DIM;
    const size_t br0 = ((size_t)e * H_DIM + col0 + lr) * I_DIM;
    const size_t br1 = ((size_t)e * H_DIM + col0 + lr + 64) * I_DIM;

    const uint32_t oA0 = chunk_off(lr, c4), oA1 = chunk_off(lr + 64, c4);

    float acc[2][8][4];
    #pragma unroll
    for (int a = 0; a < 2; a++)
        #pragma unroll
        for (int b = 0; b < 8; b++)
            #pragma unroll
            for (int c = 0; c < 4; c++) acc[a][b][c] = 0.f;

    const int NCH = I_DIM / 32;
    {
        const int gc = c4 * 8;
        uint32_t s = sbu;
        cp16(s + SA_HI + oA0, g_Hh + ar0 + gc, v0 ? 16 : 0);
        cp16(s + SA_HI + oA1, g_Hh + ar1 + gc, v1 ? 16 : 0);
        cp16(s + SB_HI + oA0, g_Dh + br0 + gc, 16);
        cp16(s + SB_HI + oA1, g_Dh + br1 + gc, 16);
        cp16(s + SB_LO + oA0, g_Dl + br0 + gc, 16);
        cp16(s + SB_LO + oA1, g_Dl + br1 + gc, 16);
        CP_COMMIT();
    }

    #pragma unroll 1
    for (int ch = 0; ch < NCH; ch++) {
        if (ch + 1 < NCH) {
            const int gc = (ch + 1) * 32 + c4 * 8;
            uint32_t s = sbu + ((ch + 1) & 1) * ST_SZ;
            cp16(s + SA_HI + oA0, g_Hh + ar0 + gc, v0 ? 16 : 0);
            cp16(s + SA_HI + oA1, g_Hh + ar1 + gc, v1 ? 16 : 0);
            cp16(s + SB_HI + oA0, g_Dh + br0 + gc, 16);
            cp16(s + SB_HI + oA1, g_Dh + br1 + gc, 16);
            cp16(s + SB_LO + oA0, g_Dl + br0 + gc, 16);
            cp16(s + SB_LO + oA1, g_Dl + br1 + gc, 16);
            CP_COMMIT();
            CP_WAIT1();
        } else {
            CP_WAIT0();
        }
        __syncthreads();
        const char* s = smem + (ch & 1) * ST_SZ;
        #pragma unroll
        for (int kh = 0; kh < 32; kh += 16) {
            uint32_t Ah[2][4];
            const int kl = kh + tg * 2, kk = kh + tg * 2 + 8;
            #pragma unroll
            for (int mt = 0; mt < 2; mt++) {
                const int r0 = wm * 32 + mt * 16 + g;
                Ah[mt][0] = lds_u32(s, SA_HI + elem_off(r0,     kl));
                Ah[mt][1] = lds_u32(s, SA_HI + elem_off(r0 + 8, kl));
                Ah[mt][2] = lds_u32(s, SA_HI + elem_off(r0,     kk));
                Ah[mt][3] = lds_u32(s, SA_HI + elem_off(r0 + 8, kk));
            }
            #pragma unroll
            for (int nt = 0; nt < 8; nt++) {
                const int n = wn * 64 + nt * 8 + g;
                const uint32_t Bh0 = lds_u32(s, SB_HI + elem_off(n, kl));
                const uint32_t Bh1 = lds_u32(s, SB_HI + elem_off(n, kk));
                const uint32_t Bl0 = lds_u32(s, SB_LO + elem_off(n, kl));
                const uint32_t Bl1 = lds_u32(s, SB_LO + elem_off(n, kk));
                #pragma unroll
                for (int mt = 0; mt < 2; mt++) {
                    mma16816(acc[mt][nt], Ah[mt], Bh0, Bh1);
                    mma16816(acc[mt][nt], Ah[mt], Bl0, Bl1);
                }
            }
        }
        __syncthreads();
    }

    #pragma unroll
    for (int mt = 0; mt < 2; mt++) {
        #pragma unroll
        for (int nt = 0; nt < 8; nt++) {
            const int r   = wm * 32 + mt * 16 + g;
            const int col = col0 + wn * 64 + nt * 8 + tg * 2;
            const float* c = acc[mt][nt];
            #pragma unroll
            for (int hrow = 0; hrow < 2; hrow++) {
                const int rr = r + hrow * 8;
                if (row0 + rr < nrows) {
                    float2 v = make_float2(c[hrow * 2], c[hrow * 2 + 1]);
                    *(float2*)(g_pout + (size_t)(start + row0 + rr) * H_DIM + col) = v;
                }
            }
        }
    }
}

// ============================================================================
// Reduce: out[t,h] = sum_k w[t,k] * g_pout[pos_of[t,k], h]  (deterministic)
// ============================================================================
__global__ void reduce_kernel(const float* __restrict__ wts, float* __restrict__ out) {
    const int i = blockIdx.x * blockDim.x + threadIdx.x;
    if (i >= T_TOK * H_DIM / 4) return;
    const int t  = i / (H_DIM / 4);
    const int h4 = (i % (H_DIM / 4)) * 4;
    float4 acc = make_float4(0.f, 0.f, 0.f, 0.f);
    #pragma unroll
    for (int k = 0; k < TOPK; k++) {
        const int   pos = g_pos_of[t * TOPK + k];
        const float w   = wts[t * TOPK + k];
        const float4 v  = *(const float4*)(g_pout + (size_t)pos * H_DIM + h4);
        acc.x = fmaf(w, v.x, acc.x);
        acc.y = fmaf(w, v.y, acc.y);
        acc.z = fmaf(w, v.z, acc.z);
        acc.w = fmaf(w, v.w, acc.w);
    }
    *(float4*)(out + (size_t)t * H_DIM + h4) = acc;
}

// ============================================================================
// Launch (graph-capturable: kernel launches only)
// ============================================================================
extern "C" void kernel_launch(void* const* d_in, const int* in_sizes, int n_in,
                              void* d_out, int out_size)
{
    const float* hidden  = (const float*)d_in[0];
    const int*   idx     = (const int*)  d_in[1];
    const float* wts     = (const float*)d_in[2];
    const float* gate_up = (const float*)d_in[3];
    const float* down    = (const float*)d_in[4];
    float*       out     = (float*)d_out;

    static bool attr_done = false;
    if (!attr_done) {
        cudaFuncSetAttribute(gemm1_mma, cudaFuncAttributeMaxDynamicSharedMemorySize, SM_TOTAL);
        cudaFuncSetAttribute(gemm2_mma, cudaFuncAttributeMaxDynamicSharedMemorySize, SM_TOTAL);
        attr_done = true;
    }

    routing_kernel<<<1, 256>>>(idx);

    {
        __half *xh, *gh, *gl, *dh, *dl;
        cudaGetSymbolAddress((void**)&xh, g_Xh);
        cudaGetSymbolAddress((void**)&gh, g_GUh); cudaGetSymbolAddress((void**)&gl, g_GUl);
        cudaGetSymbolAddress((void**)&dh, g_Dh);  cudaGetSymbolAddress((void**)&dl, g_Dl);
        const int n4x = T_TOK * H_DIM / 4;
        const int n4g = N_EXP * 2 * I_DIM * H_DIM / 4;
        const int n4d = N_EXP * H_DIM * I_DIM / 4;
        split2_kernel<<<(n4g + 255) / 256, 256>>>(gate_up, gh, gl, n4g);
        split2_kernel<<<(n4d + 255) / 256, 256>>>(down,    dh, dl, n4d);
        split1_kernel<<<(n4x + 255) / 256, 256>>>(hidden,  xh, n4x);
    }

    dim3 g1(I_DIM / 64, NPAIR / 128, N_EXP);
    gemm1_mma<<<g1, 256, SM_TOTAL>>>();

    dim3 g2(H_DIM / 128, NPAIR / 128, N_EXP);
    gemm2_mma<<<g2, 256, SM_TOTAL>>>();

    reduce_kernel<<<(T_TOK * H_DIM / 4 + 255) / 256, 256>>>(wts, out);
}